// round 1
// baseline (speedup 1.0000x reference)
#include <cuda_runtime.h>
#include <math.h>

#define BB 2
#define SS 2048
#define DD 1024
#define HH 16
#define HD 64

// Scratch: q,k,v in head-major [B,H,S,HD]; attn output in [B,S,D]
__device__ float g_q[BB*HH*SS*HD];
__device__ float g_k[BB*HH*SS*HD];
__device__ float g_v[BB*HH*SS*HD];
__device__ float g_attn[BB*SS*DD];

// ---------------------------------------------------------------------------
// NT SGEMM: C[m,n] = sum_k A[m,k]*W[n,k] + bias[n]
// A: [M=4096, K=1024] row-major, W: [N=1024, K=1024] row-major.
// 128x128x16 block tile, 256 threads, 8x8 per-thread micro-tile.
// mode 0: store to head-major qkv layout; mode 1: plain [row*DD+col] store.
// ---------------------------------------------------------------------------
__global__ __launch_bounds__(256) void gemm_nt(const float* __restrict__ A,
                                               const float* __restrict__ W,
                                               const float* __restrict__ bias,
                                               float* __restrict__ C,
                                               int mode)
{
    __shared__ float As[16][132];   // [k][m], stride 132 (16B aligned, bank-spread)
    __shared__ float Bs[16][132];   // [k][n]

    const int tid = threadIdx.x;
    const int tx  = tid & 15;       // column group
    const int ty  = tid >> 4;       // row group
    const int m0  = blockIdx.y * 128;
    const int n0  = blockIdx.x * 128;

    float acc[8][8];
#pragma unroll
    for (int i = 0; i < 8; ++i)
#pragma unroll
        for (int j = 0; j < 8; ++j) acc[i][j] = 0.0f;

    for (int k0 = 0; k0 < DD; k0 += 16) {
        // Load 128x16 tiles of A and W (transposed into smem). 512 float4s each.
#pragma unroll
        for (int it = 0; it < 2; ++it) {
            int f   = tid + it * 256;        // 0..511
            int row = f >> 2;                // 0..127
            int kq  = f & 3;                 // float4 slot within 16 k's
            float4 a4 = *(const float4*)&A[(size_t)(m0 + row) * DD + k0 + kq * 4];
            As[kq*4+0][row] = a4.x; As[kq*4+1][row] = a4.y;
            As[kq*4+2][row] = a4.z; As[kq*4+3][row] = a4.w;
            float4 b4 = *(const float4*)&W[(size_t)(n0 + row) * DD + k0 + kq * 4];
            Bs[kq*4+0][row] = b4.x; Bs[kq*4+1][row] = b4.y;
            Bs[kq*4+2][row] = b4.z; Bs[kq*4+3][row] = b4.w;
        }
        __syncthreads();

#pragma unroll
        for (int k = 0; k < 16; ++k) {
            float a[8], b[8];
            *(float4*)&a[0] = *(const float4*)&As[k][ty * 4];
            *(float4*)&a[4] = *(const float4*)&As[k][64 + ty * 4];
            *(float4*)&b[0] = *(const float4*)&Bs[k][tx * 4];
            *(float4*)&b[4] = *(const float4*)&Bs[k][64 + tx * 4];
#pragma unroll
            for (int i = 0; i < 8; ++i)
#pragma unroll
                for (int j = 0; j < 8; ++j)
                    acc[i][j] = fmaf(a[i], b[j], acc[i][j]);
        }
        __syncthreads();
    }

    // Epilogue: bias + store
#pragma unroll
    for (int i = 0; i < 8; ++i) {
        int row = m0 + ((i < 4) ? (ty * 4 + i) : (64 + ty * 4 + (i - 4)));
#pragma unroll
        for (int j = 0; j < 8; ++j) {
            int col = n0 + ((j < 4) ? (tx * 4 + j) : (64 + tx * 4 + (j - 4)));
            float v = acc[i][j] + bias[col];
            if (mode == 0) {
                // row = b*S + s ; col = h*HD + hd  ->  [B,H,S,HD]
                int b  = row >> 11;          // /2048
                int s  = row & 2047;
                int h_ = col >> 6;           // /64
                int hd = col & 63;
                C[((size_t)(b * HH + h_) * SS + s) * HD + hd] = v;
            } else {
                C[(size_t)row * DD + col] = v;
            }
        }
    }
}

// ---------------------------------------------------------------------------
// Flash attention, fp32. One block = one (b,h) and one 64-row q tile.
// 256 threads; thread owns 4x4 micro-tile: rows {ty+16*ii}, cols {tx+16*jj}.
// Online softmax, causal mask on diagonal tile only, k-loop ends at diagonal.
// ---------------------------------------------------------------------------
__global__ __launch_bounds__(256) void attn_kernel()
{
    extern __shared__ float sm[];
    const int STR = 68;                  // row stride: 16B aligned, banks spread
    float* Qs = sm;                      // 64 x STR
    float* Ks = Qs + 64 * STR;
    float* Vs = Ks + 64 * STR;
    float* Ps = Vs + 64 * STR;

    const int qt = blockIdx.x;           // q tile (0..31)
    const int bh = blockIdx.y;           // b*H + h (0..31)
    const int q0 = qt * 64;

    const float* qp = g_q + (size_t)bh * SS * HD;
    const float* kp = g_k + (size_t)bh * SS * HD;
    const float* vp = g_v + (size_t)bh * SS * HD;

    const int tid = threadIdx.x;
    const int tx  = tid & 15;
    const int ty  = tid >> 4;

    // Load Q tile (64x64 floats = 1024 float4s)
#pragma unroll
    for (int it = 0; it < 4; ++it) {
        int f   = tid + it * 256;
        int row = f >> 4;
        int dq  = f & 15;
        *(float4*)&Qs[row * STR + dq * 4] =
            *(const float4*)&qp[(size_t)(q0 + row) * HD + dq * 4];
    }

    float m_r[4], l_r[4], o_acc[4][4];
#pragma unroll
    for (int ii = 0; ii < 4; ++ii) {
        m_r[ii] = -1e30f; l_r[ii] = 0.0f;
#pragma unroll
        for (int jj = 0; jj < 4; ++jj) o_acc[ii][jj] = 0.0f;
    }

    const float scale = 0.125f;          // 1/sqrt(64)

    for (int kt = 0; kt <= qt; ++kt) {
        const int k0 = kt * 64;
        // Load K, V tiles
#pragma unroll
        for (int it = 0; it < 4; ++it) {
            int f   = tid + it * 256;
            int row = f >> 4;
            int dq  = f & 15;
            *(float4*)&Ks[row * STR + dq * 4] =
                *(const float4*)&kp[(size_t)(k0 + row) * HD + dq * 4];
            *(float4*)&Vs[row * STR + dq * 4] =
                *(const float4*)&vp[(size_t)(k0 + row) * HD + dq * 4];
        }
        __syncthreads();

        // Scores: s[ii][jj] = Q[row_i] . K[col_j]
        float s[4][4];
#pragma unroll
        for (int ii = 0; ii < 4; ++ii)
#pragma unroll
            for (int jj = 0; jj < 4; ++jj) s[ii][jj] = 0.0f;

#pragma unroll
        for (int d = 0; d < 64; d += 4) {
            float4 q4[4], k4[4];
#pragma unroll
            for (int ii = 0; ii < 4; ++ii)
                q4[ii] = *(const float4*)&Qs[(ty + 16 * ii) * STR + d];
#pragma unroll
            for (int jj = 0; jj < 4; ++jj)
                k4[jj] = *(const float4*)&Ks[(tx + 16 * jj) * STR + d];
#pragma unroll
            for (int ii = 0; ii < 4; ++ii)
#pragma unroll
                for (int jj = 0; jj < 4; ++jj) {
                    s[ii][jj] = fmaf(q4[ii].x, k4[jj].x, s[ii][jj]);
                    s[ii][jj] = fmaf(q4[ii].y, k4[jj].y, s[ii][jj]);
                    s[ii][jj] = fmaf(q4[ii].z, k4[jj].z, s[ii][jj]);
                    s[ii][jj] = fmaf(q4[ii].w, k4[jj].w, s[ii][jj]);
                }
        }

        // Scale + causal mask (diagonal tile only)
        const bool diag = (kt == qt);
#pragma unroll
        for (int ii = 0; ii < 4; ++ii) {
            int grow = q0 + ty + 16 * ii;
#pragma unroll
            for (int jj = 0; jj < 4; ++jj) {
                int gcol = k0 + tx + 16 * jj;
                float v = s[ii][jj] * scale;
                if (diag && gcol > grow) v = -1e30f;
                s[ii][jj] = v;
            }
        }

        // Online softmax per row
#pragma unroll
        for (int ii = 0; ii < 4; ++ii) {
            float mt = fmaxf(fmaxf(s[ii][0], s[ii][1]), fmaxf(s[ii][2], s[ii][3]));
#pragma unroll
            for (int off = 8; off > 0; off >>= 1)
                mt = fmaxf(mt, __shfl_xor_sync(0xffffffffu, mt, off));
            float mn = fmaxf(m_r[ii], mt);
            float alpha = __expf(m_r[ii] - mn);
            m_r[ii] = mn;
            l_r[ii] *= alpha;
#pragma unroll
            for (int jj = 0; jj < 4; ++jj) o_acc[ii][jj] *= alpha;

            float rs = 0.0f;
#pragma unroll
            for (int jj = 0; jj < 4; ++jj) {
                float p = __expf(s[ii][jj] - mn);
                s[ii][jj] = p;
                rs += p;
            }
#pragma unroll
            for (int off = 8; off > 0; off >>= 1)
                rs += __shfl_xor_sync(0xffffffffu, rs, off);
            l_r[ii] += rs;

#pragma unroll
            for (int jj = 0; jj < 4; ++jj)
                Ps[(ty + 16 * ii) * STR + tx + 16 * jj] = s[ii][jj];
        }
        __syncthreads();

        // PV: o_acc[ii][jj] += sum_k P[row_i][k] * V[k][col_j]
#pragma unroll
        for (int k = 0; k < 64; k += 4) {
            float4 p4[4];
#pragma unroll
            for (int ii = 0; ii < 4; ++ii)
                p4[ii] = *(const float4*)&Ps[(ty + 16 * ii) * STR + k];
#pragma unroll
            for (int t = 0; t < 4; ++t) {
                float vv[4];
#pragma unroll
                for (int jj = 0; jj < 4; ++jj)
                    vv[jj] = Vs[(k + t) * STR + tx + 16 * jj];
#pragma unroll
                for (int ii = 0; ii < 4; ++ii) {
                    const float* pf = (const float*)&p4[ii];
                    float pv = pf[t];
#pragma unroll
                    for (int jj = 0; jj < 4; ++jj)
                        o_acc[ii][jj] = fmaf(pv, vv[jj], o_acc[ii][jj]);
                }
            }
        }
        __syncthreads();
    }

    // Normalize and write to [B,S,D]
    const int b  = bh >> 4;
    const int h_ = bh & 15;
#pragma unroll
    for (int ii = 0; ii < 4; ++ii) {
        float inv = 1.0f / l_r[ii];
        int row = q0 + ty + 16 * ii;
#pragma unroll
        for (int jj = 0; jj < 4; ++jj) {
            int col = tx + 16 * jj;
            g_attn[((size_t)b * SS + row) * DD + h_ * HD + col] = o_acc[ii][jj] * inv;
        }
    }
}

// ---------------------------------------------------------------------------
extern "C" void kernel_launch(void* const* d_in, const int* in_sizes, int n_in,
                              void* d_out, int out_size)
{
    const float* h  = (const float*)d_in[0];
    const float* Wq = (const float*)d_in[1];
    const float* bq = (const float*)d_in[2];
    const float* Wk = (const float*)d_in[3];
    const float* bk = (const float*)d_in[4];
    const float* Wv = (const float*)d_in[5];
    const float* bv = (const float*)d_in[6];
    const float* Wo = (const float*)d_in[7];
    const float* bo = (const float*)d_in[8];
    float* out = (float*)d_out;

    float *dq, *dk, *dv, *da;
    cudaGetSymbolAddress((void**)&dq, g_q);
    cudaGetSymbolAddress((void**)&dk, g_k);
    cudaGetSymbolAddress((void**)&dv, g_v);
    cudaGetSymbolAddress((void**)&da, g_attn);

    dim3 ggrid(DD / 128, (BB * SS) / 128);   // (8, 32)

    gemm_nt<<<ggrid, 256>>>(h, Wq, bq, dq, 0);
    gemm_nt<<<ggrid, 256>>>(h, Wk, bk, dk, 0);
    gemm_nt<<<ggrid, 256>>>(h, Wv, bv, dv, 0);

    const int ATTN_SMEM = 4 * 64 * 68 * (int)sizeof(float);   // 69632 B
    cudaFuncSetAttribute(attn_kernel, cudaFuncAttributeMaxDynamicSharedMemorySize,
                         ATTN_SMEM);
    attn_kernel<<<dim3(SS / 64, BB * HH), 256, ATTN_SMEM>>>();

    gemm_nt<<<ggrid, 256>>>(da, Wo, bo, out, 1);
}